// round 10
// baseline (speedup 1.0000x reference)
#include <cuda_runtime.h>
#include <cuda_bf16.h>
#include <cstdint>
#include <math.h>

#define VOCAB 100000
#define HID   128
#define BATCH 1024

// intermediate h_new (fp32) between the two kernels
__device__ float g_hnew[BATCH * HID];

__device__ __forceinline__ uint32_t f2tf32(float x) {
    uint32_t r;
    asm("cvt.rna.tf32.f32 %0, %1;" : "=r"(r) : "f"(x));
    return r;
}

// ---------------------------------------------------------------------------
// Kernel 1: GRU cell -> h_new  (64 CTAs x 256 thr, 16 batches per CTA)
// ---------------------------------------------------------------------------
#define BPB         16
#define GRU_THREADS 256
#define WHS_STRIDE  129   // pad to kill 32-way bank conflicts
#define GHS_STRIDE  33
#define GRU_SMEM    ((384 * WHS_STRIDE + BPB * HID) * 4)   // 206,336 B

__global__ __launch_bounds__(GRU_THREADS, 1)
void gru_kernel(const int*   __restrict__ inp,
                const float* __restrict__ hid,
                const float* __restrict__ Wih,
                const float* __restrict__ bih,
                const float* __restrict__ Whh,
                const float* __restrict__ bhh,
                float*       __restrict__ out_hidden) {
    extern __shared__ float sm[];
    float* whs  = sm;                        // [384][129]
    float* h0sT = sm + 384 * WHS_STRIDE;     // [128 k][16 bl] (transposed)
    float* ghs  = sm;                        // overlay after phase 2: [384][33]

    const int tid = threadIdx.x;
    const int b0  = blockIdx.x * BPB;

    // Phase 1: stage W_hh (coalesced) + transposed h0
    for (int idx = tid; idx < 384 * HID; idx += GRU_THREADS) {
        int j = idx >> 7, k = idx & 127;
        whs[j * WHS_STRIDE + k] = Whh[idx];
    }
    for (int idx = tid; idx < BPB * HID; idx += GRU_THREADS) {
        int bl = idx >> 7, k = idx & 127;
        h0sT[k * BPB + bl] = hid[(b0 + bl) * HID + k];
    }
    __syncthreads();

    // Phase 2: gh[b][j] = h0 . W_hh[j] + b_hh[j]; each thread: 3 x (j, 8 batches)
    float acc[3][8];
#pragma unroll
    for (int it = 0; it < 3; it++) {
        int task = tid + it * GRU_THREADS;      // 0..767 = 384 j x 2 bgroups
        int j = task % 384, g = task / 384;
        float bb = bhh[j];
#pragma unroll
        for (int u = 0; u < 8; u++) acc[it][u] = bb;
        const float* hb = h0sT + g * 8;
        for (int k = 0; k < HID; k++) {
            float  w  = whs[j * WHS_STRIDE + k];
            float4 h0 = *(const float4*)(hb + k * BPB);
            float4 h1 = *(const float4*)(hb + k * BPB + 4);
            acc[it][0] += h0.x * w;  acc[it][1] += h0.y * w;
            acc[it][2] += h0.z * w;  acc[it][3] += h0.w * w;
            acc[it][4] += h1.x * w;  acc[it][5] += h1.y * w;
            acc[it][6] += h1.z * w;  acc[it][7] += h1.w * w;
        }
    }
    __syncthreads();        // whs now dead
#pragma unroll
    for (int it = 0; it < 3; it++) {
        int task = tid + it * GRU_THREADS;
        int j = task % 384, g = task / 384;
#pragma unroll
        for (int u = 0; u < 8; u++)
            ghs[j * GHS_STRIDE + g * 8 + u] = acc[it][u];
    }
    __syncthreads();

    // Phase 3: gates + h_new; gi via row-gather of W_ih at column input[b]
    for (int it = 0; it < (BPB * HID) / GRU_THREADS; it++) {   // 8
        int idx = tid + it * GRU_THREADS;
        int bl = idx >> 7, i = idx & 127;
        int b = b0 + bl;
        int v = inp[b];
        float gr  = Wih[(size_t)i * VOCAB + v]         + bih[i]       + ghs[i * GHS_STRIDE + bl];
        float gz  = Wih[(size_t)(i + 128) * VOCAB + v] + bih[i + 128] + ghs[(i + 128) * GHS_STRIDE + bl];
        float gin = Wih[(size_t)(i + 256) * VOCAB + v] + bih[i + 256];
        float ghn = ghs[(i + 256) * GHS_STRIDE + bl];
        float r = 1.f / (1.f + expf(-gr));
        float z = 1.f / (1.f + expf(-gz));
        float n = tanhf(gin + r * ghn);
        float h0v = h0sT[i * BPB + bl];
        float hn = (1.f - z) * n + z * h0v;
        g_hnew[b * HID + i]     = hn;
        out_hidden[b * HID + i] = hn;
    }
}

// ---------------------------------------------------------------------------
// Kernel 2: logits = ReLU(h_new @ W_out^T + b_out) via mma.sync tf32
//   CTA tile 128x128x128, 8 warps (4m x 2n), warp tile 32x64, m16n8k8
// ---------------------------------------------------------------------------
#define TSTR      132                                // smem row stride (floats)
#define NBT       ((VOCAB + 127) / 128)              // 782 n-tiles
#define GEMM_SMEM ((2 * 128 * TSTR + 128) * 4)       // 135,680 B

__device__ __forceinline__ void mma_tf32(float c[4],
                                         uint32_t a0, uint32_t a1, uint32_t a2, uint32_t a3,
                                         uint32_t b0, uint32_t b1) {
    asm volatile(
        "mma.sync.aligned.m16n8k8.row.col.f32.tf32.tf32.f32 "
        "{%0,%1,%2,%3}, {%4,%5,%6,%7}, {%8,%9}, {%0,%1,%2,%3};"
        : "+f"(c[0]), "+f"(c[1]), "+f"(c[2]), "+f"(c[3])
        : "r"(a0), "r"(a1), "r"(a2), "r"(a3), "r"(b0), "r"(b1));
}

__global__ __launch_bounds__(256, 1)
void gemm_out_kernel(const float* __restrict__ Wout,
                     const float* __restrict__ bout,
                     float*       __restrict__ out) {
    extern __shared__ uint32_t smw[];
    uint32_t* As = smw;                     // [128 m][132] tf32
    uint32_t* Bs = smw + 128 * TSTR;        // [128 n][132] tf32
    float*    bs = (float*)(smw + 2 * 128 * TSTR);   // [128] bias

    const int tid = threadIdx.x;
    // mb fastest: 8 CTAs sharing a W_out tile run in the same wave (L2 reuse)
    const int mb = blockIdx.x & 7;
    const int nb = blockIdx.x >> 3;

    // ---- stage A tile: h_new[mb*128 .. +128][0..128) -> tf32
#pragma unroll
    for (int i = 0; i < 16; i++) {
        int idx = tid + (i << 8);            // 0..4095 float4s
        int r  = idx >> 5;
        int kq = (idx & 31) << 2;
        float4 a = *(const float4*)(g_hnew + ((size_t)(mb * 128 + r) << 7) + kq);
        *(uint4*)(As + r * TSTR + kq) =
            make_uint4(f2tf32(a.x), f2tf32(a.y), f2tf32(a.z), f2tf32(a.w));
    }
    // ---- stage B tile: W_out[nb*128 .. +128][0..128) -> tf32 (guarded)
#pragma unroll
    for (int i = 0; i < 16; i++) {
        int idx = tid + (i << 8);
        int r  = idx >> 5;
        int kq = (idx & 31) << 2;
        int n  = nb * 128 + r;
        float4 b = make_float4(0.f, 0.f, 0.f, 0.f);
        if (n < VOCAB) b = *(const float4*)(Wout + (size_t)n * HID + kq);
        *(uint4*)(Bs + r * TSTR + kq) =
            make_uint4(f2tf32(b.x), f2tf32(b.y), f2tf32(b.z), f2tf32(b.w));
    }
    if (tid < 128) {
        int n = nb * 128 + tid;
        bs[tid] = (n < VOCAB) ? bout[n] : 0.f;
    }
    __syncthreads();

    // ---- warp tiling: 4m x 2n warps, each 32x64
    const int w    = tid >> 5;
    const int lane = tid & 31;
    const int mw   = w >> 1;        // 0..3
    const int nw   = w & 1;         // 0..1
    const int g    = lane >> 2;     // 0..7
    const int t    = lane & 3;      // 0..3

    const uint32_t* Ap = As + (mw * 32 + g) * TSTR + t;   // a0 of mi=0
    const uint32_t* Bp = Bs + (nw * 64 + g) * TSTR + t;   // b0 of ni=0

    float c[2][8][4];
#pragma unroll
    for (int mi = 0; mi < 2; mi++)
#pragma unroll
        for (int ni = 0; ni < 8; ni++)
#pragma unroll
            for (int q = 0; q < 4; q++) c[mi][ni][q] = 0.f;

#pragma unroll
    for (int ks = 0; ks < 16; ks++) {
        const int kb = ks * 8;
        uint32_t a[2][4], b[8][2];
#pragma unroll
        for (int mi = 0; mi < 2; mi++) {
            const uint32_t* p = Ap + mi * 16 * TSTR + kb;
            a[mi][0] = p[0];
            a[mi][1] = p[8 * TSTR];
            a[mi][2] = p[4];
            a[mi][3] = p[8 * TSTR + 4];
        }
#pragma unroll
        for (int ni = 0; ni < 8; ni++) {
            const uint32_t* p = Bp + ni * 8 * TSTR + kb;
            b[ni][0] = p[0];
            b[ni][1] = p[4];
        }
#pragma unroll
        for (int mi = 0; mi < 2; mi++)
#pragma unroll
            for (int ni = 0; ni < 8; ni++)
                mma_tf32(c[mi][ni], a[mi][0], a[mi][1], a[mi][2], a[mi][3],
                         b[ni][0], b[ni][1]);
    }

    // ---- epilogue: bias + ReLU, streaming stores (full 32B sectors per quad)
#pragma unroll
    for (int mi = 0; mi < 2; mi++) {
        int row0 = mb * 128 + mw * 32 + mi * 16 + g;
        float* d0 = out + (size_t)row0 * VOCAB;
        float* d1 = d0 + 8 * VOCAB;
#pragma unroll
        for (int ni = 0; ni < 8; ni++) {
            int colb = nw * 64 + ni * 8 + 2 * t;
            int col  = nb * 128 + colb;
            if (col < VOCAB) {               // VOCAB even, col even -> pair safe
                float b0 = bs[colb], b1 = bs[colb + 1];
                float2 v0 = make_float2(fmaxf(c[mi][ni][0] + b0, 0.f),
                                        fmaxf(c[mi][ni][1] + b1, 0.f));
                float2 v1 = make_float2(fmaxf(c[mi][ni][2] + b0, 0.f),
                                        fmaxf(c[mi][ni][3] + b1, 0.f));
                __stcs((float2*)(d0 + col), v0);   // evict-first: protect W_out L2
                __stcs((float2*)(d1 + col), v1);
            }
        }
    }
}

// ---------------------------------------------------------------------------
// launch
// ---------------------------------------------------------------------------
extern "C" void kernel_launch(void* const* d_in, const int* in_sizes, int n_in,
                              void* d_out, int out_size) {
    const int*   inp  = (const int*)  d_in[0];
    const float* hid  = (const float*)d_in[1];
    const float* Wih  = (const float*)d_in[2];
    const float* bih  = (const float*)d_in[3];
    const float* Whh  = (const float*)d_in[4];
    const float* bhh  = (const float*)d_in[5];
    const float* Wout = (const float*)d_in[6];
    const float* bout = (const float*)d_in[7];
    float* out = (float*)d_out;

    cudaFuncSetAttribute(gru_kernel, cudaFuncAttributeMaxDynamicSharedMemorySize, GRU_SMEM);
    cudaFuncSetAttribute(gemm_out_kernel, cudaFuncAttributeMaxDynamicSharedMemorySize, GEMM_SMEM);

    // output layout: [logits (1024 x 100000) | hidden (1 x 1024 x 128)]
    gru_kernel<<<BATCH / BPB, GRU_THREADS, GRU_SMEM>>>(
        inp, hid, Wih, bih, Whh, bhh, out + (size_t)BATCH * VOCAB);
    gemm_out_kernel<<<NBT * 8, 256, GEMM_SMEM>>>(Wout, bout, out);
}